// round 5
// baseline (speedup 1.0000x reference)
#include <cuda_runtime.h>
#include <math.h>
#include <stdint.h>

#define D_MODEL   1024
#define NUM_HEADS 16
#define HEAD_DIM  64
#define BATCH     2
#define SEQ       2048
#define MROWS     (BATCH*SEQ)   /* 4096 */

// ---------------------------------------------------------------------------
// Scratch (allocation-free: __device__ globals)
// ---------------------------------------------------------------------------
__device__ float g_Q[MROWS * D_MODEL];
__device__ float g_K[MROWS * D_MODEL];
__device__ float g_V[MROWS * D_MODEL];
__device__ float g_AO[MROWS * D_MODEL];

extern __shared__ uint32_t dynsmem[];

// ---------------------------------------------------------------------------
// helpers
// ---------------------------------------------------------------------------
__device__ __forceinline__ uint32_t smem_u32(const void* p) {
    uint32_t a;
    asm("{ .reg .u64 t; cvta.to.shared.u64 t, %1; cvt.u32.u64 %0, t; }" : "=r"(a) : "l"(p));
    return a;
}
__device__ __forceinline__ uint32_t f2tf32(float f) {
    uint32_t r;
    asm("cvt.rna.tf32.f32 %0, %1;" : "=r"(r) : "f"(f));
    return r;
}
__device__ __forceinline__ void cpasync16(uint32_t s, const void* g) {
    asm volatile("cp.async.ca.shared.global [%0], [%1], 16;" :: "r"(s), "l"(g) : "memory");
}
__device__ __forceinline__ void cp_commit() { asm volatile("cp.async.commit_group;" ::: "memory"); }
__device__ __forceinline__ void cp_wait0()  { asm volatile("cp.async.wait_group 0;" ::: "memory"); }

__device__ __forceinline__ void mma_tf32(float c[4], uint32_t a0, uint32_t a1,
                                         uint32_t a2, uint32_t a3,
                                         uint32_t b0, uint32_t b1) {
    asm volatile(
        "mma.sync.aligned.m16n8k8.row.col.f32.tf32.tf32.f32 "
        "{%0,%1,%2,%3}, {%4,%5,%6,%7}, {%8,%9}, {%0,%1,%2,%3};"
        : "+f"(c[0]), "+f"(c[1]), "+f"(c[2]), "+f"(c[3])
        : "r"(a0), "r"(a1), "r"(a2), "r"(a3), "r"(b0), "r"(b1));
}

// ---------------------------------------------------------------------------
// tf32 mma.sync GEMM: C[M,1024] = A[M,1024] @ W[1024,1024]^T
// CTA tile 128x256, 8 warps (warp tile 64x64), BK=16, cp.async double buffer,
// in-place fp32->tf32 conversion pass (no cvt in the MMA loop).
// Optional fused RoPE on the output (for Q/K projections).
// ---------------------------------------------------------------------------
#define GBK     16
#define GSTR    20
#define G_ABUF  (128 * GSTR)            /* 2560 u32 per A buffer */
#define G_BBUF  (256 * GSTR)            /* 5120 u32 per B buffer */
#define G_BUF   (G_ABUF + G_BBUF)       /* 7680 */
#define GEMM_SMEM (2 * G_BUF * 4)       /* 61440 B */
#define GNT     (D_MODEL / GBK)         /* 64 */

__device__ __forceinline__ void gemm_mma_core(const float* __restrict__ A,
                                              const float* __restrict__ W,
                                              float* __restrict__ C,
                                              const int* __restrict__ pos,
                                              int apply_rope)
{
    uint32_t* sm = dynsmem;
    const int tid   = threadIdx.x;
    const int lane  = tid & 31;
    const int wid   = tid >> 5;
    const int warpM = wid & 1;
    const int warpN = wid >> 1;
    const int gid   = lane >> 2;
    const int tig   = lane & 3;
    const int m0    = blockIdx.y * 128;
    const int n0    = blockIdx.x * 256;

    const uint32_t smbase = smem_u32(sm);
    const int arow = tid >> 2;          // 0..63
    const int ac4  = (tid & 3) * 4;     // 0,4,8,12

    float acc[4][8][4];
#pragma unroll
    for (int i = 0; i < 4; i++)
#pragma unroll
        for (int j = 0; j < 8; j++)
#pragma unroll
            for (int q = 0; q < 4; q++) acc[i][j][q] = 0.0f;

    // ---- issue tile t into buffer b ----
    auto issue_tile = [&](int t, int b) {
        const int k0 = t * GBK;
        const uint32_t abase = smbase + (uint32_t)(b * G_BUF) * 4;
        const uint32_t bbase = abase + G_ABUF * 4;
        cpasync16(abase + (uint32_t)(arow * GSTR + ac4) * 4,
                  &A[(size_t)(m0 + arow) * D_MODEL + k0 + ac4]);
        cpasync16(abase + (uint32_t)((arow + 64) * GSTR + ac4) * 4,
                  &A[(size_t)(m0 + arow + 64) * D_MODEL + k0 + ac4]);
#pragma unroll
        for (int it = 0; it < 4; it++) {
            const int row = arow + it * 64;
            cpasync16(bbase + (uint32_t)(row * GSTR + ac4) * 4,
                      &W[(size_t)(n0 + row) * D_MODEL + k0 + ac4]);
        }
        cp_commit();
    };

    issue_tile(0, 0);

    for (int t = 0; t < GNT; t++) {
        const int b = t & 1;
        cp_wait0();
        __syncthreads();
        if (t + 1 < GNT) issue_tile(t + 1, b ^ 1);

        // in-place fp32 -> tf32 (rna) conversion of buffer b
        {
            uint32_t* bp = sm + b * G_BUF;
#pragma unroll
            for (int it = 0; it < 6; it++) {
                int off;
                if (it < 2) {
                    const int id = tid + it * 256;          // A: 512 float4 slots
                    off = (id >> 2) * GSTR + (id & 3) * 4;
                } else {
                    const int id = tid + (it - 2) * 256;    // B: 1024 slots
                    off = G_ABUF + (id >> 2) * GSTR + (id & 3) * 4;
                }
                float4 v = *(float4*)&bp[off];
                uint4 u;
                u.x = f2tf32(v.x); u.y = f2tf32(v.y);
                u.z = f2tf32(v.z); u.w = f2tf32(v.w);
                *(uint4*)&bp[off] = u;
            }
        }
        __syncthreads();

        const uint32_t* Ab = sm + b * G_BUF;
        const uint32_t* Bb = Ab + G_ABUF;
#pragma unroll
        for (int ks = 0; ks < 2; ks++) {
            const int k0 = ks * 8;
            uint32_t af[4][4], bf[8][2];
#pragma unroll
            for (int mf = 0; mf < 4; mf++) {
                const int ra = warpM * 64 + mf * 16 + gid;
                af[mf][0] = Ab[ra * GSTR + k0 + tig];
                af[mf][1] = Ab[(ra + 8) * GSTR + k0 + tig];
                af[mf][2] = Ab[ra * GSTR + k0 + tig + 4];
                af[mf][3] = Ab[(ra + 8) * GSTR + k0 + tig + 4];
            }
#pragma unroll
            for (int nf = 0; nf < 8; nf++) {
                const int rb = warpN * 64 + nf * 8 + gid;
                bf[nf][0] = Bb[rb * GSTR + k0 + tig];
                bf[nf][1] = Bb[rb * GSTR + k0 + tig + 4];
            }
#pragma unroll
            for (int mf = 0; mf < 4; mf++)
#pragma unroll
                for (int nf = 0; nf < 8; nf++)
                    mma_tf32(acc[mf][nf], af[mf][0], af[mf][1], af[mf][2], af[mf][3],
                             bf[nf][0], bf[nf][1]);
        }
    }

    // ---- epilogue (optional fused RoPE) ----
    float ivf[8];
    if (apply_rope) {
#pragma unroll
        for (int nf = 0; nf < 8; nf++)
            ivf[nf] = (float)exp(-(double)(4 * nf + tig) * (9.210340371976184 / 32.0));
    }

#pragma unroll
    for (int mf = 0; mf < 4; mf++) {
        const int r = m0 + warpM * 64 + mf * 16 + gid;
        float p0 = 0.f, p8 = 0.f;
        if (apply_rope) {
            p0 = (float)pos[r & (SEQ - 1)];
            p8 = (float)pos[(r + 8) & (SEQ - 1)];
        }
#pragma unroll
        for (int nf = 0; nf < 8; nf++) {
            const int c = n0 + warpN * 64 + nf * 8 + 2 * tig;   // even column
            float x0 = acc[mf][nf][0], x1 = acc[mf][nf][1];
            float x2 = acc[mf][nf][2], x3 = acc[mf][nf][3];
            if (apply_rope) {
                float sn, cs;
                sincosf(p0 * ivf[nf], &sn, &cs);
                float t0 = x0 * cs - x1 * sn;
                float t1 = x0 * sn + x1 * cs;
                x0 = t0; x1 = t1;
                sincosf(p8 * ivf[nf], &sn, &cs);
                t0 = x2 * cs - x3 * sn;
                t1 = x2 * sn + x3 * cs;
                x2 = t0; x3 = t1;
            }
            *(float2*)&C[(size_t)r * D_MODEL + c]       = make_float2(x0, x1);
            *(float2*)&C[(size_t)(r + 8) * D_MODEL + c] = make_float2(x2, x3);
        }
    }
}

__global__ void __launch_bounds__(256)
qkv_gemm_kernel(const float* __restrict__ X,
                const float* __restrict__ Wq,
                const float* __restrict__ Wk,
                const float* __restrict__ Wv,
                const int* __restrict__ pos)
{
    const float* W = (blockIdx.z == 0) ? Wq : (blockIdx.z == 1) ? Wk : Wv;
    float* C       = (blockIdx.z == 0) ? g_Q : (blockIdx.z == 1) ? g_K : g_V;
    gemm_mma_core(X, W, C, pos, blockIdx.z < 2);
}

__global__ void __launch_bounds__(256)
o_gemm_kernel(const float* __restrict__ Wo, float* __restrict__ out)
{
    gemm_mma_core(g_AO, Wo, out, nullptr, 0);
}

// ---------------------------------------------------------------------------
// Causal flash attention, m16n8k8 tf32 mma, cp.async double-buffered K/V.
//   grid (SEQ/128, BATCH*NUM_HEADS), 256 threads (8 warps x 16 q-rows).
//   K and V in natural [key][dim] layout; V consumed with swapped (k,n)
//   indexing (no physical transpose). In-place tf32 convert after cp.async.
// ---------------------------------------------------------------------------
#define A_BM     128
#define A_BN     64
#define A_STR    68
#define AK_U32   (A_BN * A_STR)          /* 4352 u32 per matrix */
#define ABUF_U32 (2 * AK_U32)            /* K+V per buffer */
#define APS_OFF  (2 * ABUF_U32)          /* Ps after both buffers */
#define ATT_SMEM ((2 * ABUF_U32 + A_BM * A_STR) * 4)   /* 104448 B */

__global__ void __launch_bounds__(256)
attn_mma_kernel()
{
    uint32_t* sm = dynsmem;
    const int tid  = threadIdx.x;
    const int lane = tid & 31;
    const int w    = tid >> 5;
    const int gid  = lane >> 2;
    const int tig  = lane & 3;
    const int bh   = blockIdx.y;
    const int b    = bh >> 4;
    const int h    = bh & 15;
    const int m0   = blockIdx.x * A_BM;

    const float* __restrict__ Qb = g_Q + (size_t)b * SEQ * D_MODEL + h * HEAD_DIM;
    const float* __restrict__ Kb = g_K + (size_t)b * SEQ * D_MODEL + h * HEAD_DIM;
    const float* __restrict__ Vb = g_V + (size_t)b * SEQ * D_MODEL + h * HEAD_DIM;

    const uint32_t smbase = smem_u32(sm);
    uint32_t* Ps = sm + APS_OFF;

    // ---- async tile loader ----
    auto issue = [&](int ti, int bb) {
        const int kt = ti * A_BN;
        const uint32_t base = smbase + (uint32_t)(bb * ABUF_U32) * 4;
#pragma unroll
        for (int it = 0; it < 4; it++) {
            const int id  = tid + it * 256;
            const int row = id >> 4;
            const int c4  = (id & 15) * 4;
            cpasync16(base + (uint32_t)(row * A_STR + c4) * 4,
                      &Kb[(size_t)(kt + row) * D_MODEL + c4]);
            cpasync16(base + (uint32_t)(AK_U32 + row * A_STR + c4) * 4,
                      &Vb[(size_t)(kt + row) * D_MODEL + c4]);
        }
        cp_commit();
    };

    issue(0, 0);

    const int r0 = m0 + w * 16 + gid;
    const int r1 = r0 + 8;

    // Q fragments, pre-scaled by 1/sqrt(HEAD_DIM) (overlaps with cp.async tile 0)
    uint32_t qf[8][4];
#pragma unroll
    for (int kc = 0; kc < 8; kc++) {
        qf[kc][0] = f2tf32(0.125f * Qb[(size_t)r0 * D_MODEL + kc * 8 + tig]);
        qf[kc][1] = f2tf32(0.125f * Qb[(size_t)r1 * D_MODEL + kc * 8 + tig]);
        qf[kc][2] = f2tf32(0.125f * Qb[(size_t)r0 * D_MODEL + kc * 8 + tig + 4]);
        qf[kc][3] = f2tf32(0.125f * Qb[(size_t)r1 * D_MODEL + kc * 8 + tig + 4]);
    }

    float oacc[8][4];
#pragma unroll
    for (int nf = 0; nf < 8; nf++)
#pragma unroll
        for (int q = 0; q < 4; q++) oacc[nf][q] = 0.0f;
    float m_a = -1e30f, m_b = -1e30f, l_a = 0.0f, l_b = 0.0f;

    const int nt = (m0 + A_BM) / A_BN;

    for (int ti = 0; ti < nt; ti++) {
        const int bb = ti & 1;
        const int kt = ti * A_BN;
        cp_wait0();
        __syncthreads();
        if (ti + 1 < nt) issue(ti + 1, bb ^ 1);

        // in-place fp32 -> tf32 of buffer bb (K then V)
        {
            uint32_t* bp = sm + bb * ABUF_U32;
#pragma unroll
            for (int it = 0; it < 8; it++) {
                const int id   = (it < 4) ? tid + it * 256 : tid + (it - 4) * 256;
                const int mo   = (it < 4) ? 0 : AK_U32;
                const int row  = id >> 4;
                const int c4   = (id & 15) * 4;
                const int off  = mo + row * A_STR + c4;
                float4 v = *(float4*)&bp[off];
                uint4 u;
                u.x = f2tf32(v.x); u.y = f2tf32(v.y);
                u.z = f2tf32(v.z); u.w = f2tf32(v.w);
                *(uint4*)&bp[off] = u;
            }
        }
        __syncthreads();

        const uint32_t* Ks = sm + bb * ABUF_U32;
        const uint32_t* Vs = Ks + AK_U32;

        // --- S = Q @ K^T ---
        float sacc[8][4];
#pragma unroll
        for (int nf = 0; nf < 8; nf++)
#pragma unroll
            for (int q = 0; q < 4; q++) sacc[nf][q] = 0.0f;

#pragma unroll
        for (int kc = 0; kc < 8; kc++) {
            uint32_t bf[8][2];
#pragma unroll
            for (int nf = 0; nf < 8; nf++) {
                const int rb = nf * 8 + gid;
                bf[nf][0] = Ks[rb * A_STR + kc * 8 + tig];
                bf[nf][1] = Ks[rb * A_STR + kc * 8 + tig + 4];
            }
#pragma unroll
            for (int nf = 0; nf < 8; nf++)
                mma_tf32(sacc[nf], qf[kc][0], qf[kc][1], qf[kc][2], qf[kc][3],
                         bf[nf][0], bf[nf][1]);
        }

        // --- causal mask (last two tiles only) ---
        if (kt + A_BN - 1 > m0) {
#pragma unroll
            for (int nf = 0; nf < 8; nf++) {
                const int c = kt + nf * 8 + 2 * tig;
                if (c > r0)     sacc[nf][0] = -1e30f;
                if (c + 1 > r0) sacc[nf][1] = -1e30f;
                if (c > r1)     sacc[nf][2] = -1e30f;
                if (c + 1 > r1) sacc[nf][3] = -1e30f;
            }
        }

        // --- online softmax ---
        float mx_a = -1e30f, mx_b = -1e30f;
#pragma unroll
        for (int nf = 0; nf < 8; nf++) {
            mx_a = fmaxf(mx_a, fmaxf(sacc[nf][0], sacc[nf][1]));
            mx_b = fmaxf(mx_b, fmaxf(sacc[nf][2], sacc[nf][3]));
        }
        mx_a = fmaxf(mx_a, __shfl_xor_sync(0xFFFFFFFFu, mx_a, 1));
        mx_a = fmaxf(mx_a, __shfl_xor_sync(0xFFFFFFFFu, mx_a, 2));
        mx_b = fmaxf(mx_b, __shfl_xor_sync(0xFFFFFFFFu, mx_b, 1));
        mx_b = fmaxf(mx_b, __shfl_xor_sync(0xFFFFFFFFu, mx_b, 2));

        const float mna = fmaxf(m_a, mx_a);
        const float mnb = fmaxf(m_b, mx_b);
        const float ca  = __expf(m_a - mna);
        const float cb  = __expf(m_b - mnb);
        m_a = mna; m_b = mnb;

        float sa = 0.0f, sb = 0.0f;
#pragma unroll
        for (int nf = 0; nf < 8; nf++) {
            sacc[nf][0] = __expf(sacc[nf][0] - mna);
            sacc[nf][1] = __expf(sacc[nf][1] - mna);
            sacc[nf][2] = __expf(sacc[nf][2] - mnb);
            sacc[nf][3] = __expf(sacc[nf][3] - mnb);
            sa += sacc[nf][0] + sacc[nf][1];
            sb += sacc[nf][2] + sacc[nf][3];
        }
        sa += __shfl_xor_sync(0xFFFFFFFFu, sa, 1);
        sa += __shfl_xor_sync(0xFFFFFFFFu, sa, 2);
        sb += __shfl_xor_sync(0xFFFFFFFFu, sb, 1);
        sb += __shfl_xor_sync(0xFFFFFFFFu, sb, 2);
        l_a = l_a * ca + sa;
        l_b = l_b * cb + sb;
#pragma unroll
        for (int nf = 0; nf < 8; nf++) {
            oacc[nf][0] *= ca; oacc[nf][1] *= ca;
            oacc[nf][2] *= cb; oacc[nf][3] *= cb;
        }

        // --- stage P (tf32 bits) in smem; warp-private rows ---
        const int pr0 = w * 16 + gid;
#pragma unroll
        for (int nf = 0; nf < 8; nf++) {
            const int c = nf * 8 + 2 * tig;
            asm volatile("st.shared.v2.b32 [%0], {%1,%2};"
                :: "r"(smem_u32(&Ps[pr0 * A_STR + c])),
                   "r"(f2tf32(sacc[nf][0])), "r"(f2tf32(sacc[nf][1])) : "memory");
            asm volatile("st.shared.v2.b32 [%0], {%1,%2};"
                :: "r"(smem_u32(&Ps[(pr0 + 8) * A_STR + c])),
                   "r"(f2tf32(sacc[nf][2])), "r"(f2tf32(sacc[nf][3])) : "memory");
        }
        __syncwarp();

        // --- O += P @ V (V natural layout, swapped indexing) ---
#pragma unroll
        for (int kc = 0; kc < 8; kc++) {
            const uint32_t a0 = Ps[pr0 * A_STR + kc * 8 + tig];
            const uint32_t a1 = Ps[(pr0 + 8) * A_STR + kc * 8 + tig];
            const uint32_t a2 = Ps[pr0 * A_STR + kc * 8 + tig + 4];
            const uint32_t a3 = Ps[(pr0 + 8) * A_STR + kc * 8 + tig + 4];
            uint32_t bf[8][2];
#pragma unroll
            for (int nf = 0; nf < 8; nf++) {
                bf[nf][0] = Vs[(kc * 8 + tig) * A_STR + nf * 8 + gid];
                bf[nf][1] = Vs[(kc * 8 + tig + 4) * A_STR + nf * 8 + gid];
            }
#pragma unroll
            for (int nf = 0; nf < 8; nf++)
                mma_tf32(oacc[nf], a0, a1, a2, a3, bf[nf][0], bf[nf][1]);
        }
    }

    // --- final normalize + store ---
    const float ila = 1.0f / l_a;
    const float ilb = 1.0f / l_b;
    float* oa = g_AO + (size_t)(b * SEQ + r0) * D_MODEL + h * HEAD_DIM;
    float* ob = g_AO + (size_t)(b * SEQ + r1) * D_MODEL + h * HEAD_DIM;
#pragma unroll
    for (int nf = 0; nf < 8; nf++) {
        const int c = nf * 8 + 2 * tig;
        *(float2*)&oa[c] = make_float2(oacc[nf][0] * ila, oacc[nf][1] * ila);
        *(float2*)&ob[c] = make_float2(oacc[nf][2] * ilb, oacc[nf][3] * ilb);
    }
}

// ---------------------------------------------------------------------------
// Launch
// ---------------------------------------------------------------------------
extern "C" void kernel_launch(void* const* d_in, const int* in_sizes, int n_in,
                              void* d_out, int out_size)
{
    const float* X   = (const float*)d_in[0];
    const float* Wq  = (const float*)d_in[1];
    const float* Wk  = (const float*)d_in[2];
    const float* Wv  = (const float*)d_in[3];
    const float* Wo  = (const float*)d_in[4];
    const int*   pos = (const int*)d_in[5];
    float* out = (float*)d_out;

    static int attr_set = 0;
    if (!attr_set) {
        cudaFuncSetAttribute(qkv_gemm_kernel,
                             cudaFuncAttributeMaxDynamicSharedMemorySize, GEMM_SMEM);
        cudaFuncSetAttribute(o_gemm_kernel,
                             cudaFuncAttributeMaxDynamicSharedMemorySize, GEMM_SMEM);
        cudaFuncSetAttribute(attn_mma_kernel,
                             cudaFuncAttributeMaxDynamicSharedMemorySize, ATT_SMEM);
        attr_set = 1;
    }

    // 1) QKV projections with fused RoPE on Q/K
    dim3 ggrid(D_MODEL / 256, MROWS / 128, 3);
    qkv_gemm_kernel<<<ggrid, 256, GEMM_SMEM>>>(X, Wq, Wk, Wv, pos);

    // 2) causal attention (tf32 mma, async pipeline)
    dim3 agrid(SEQ / A_BM, BATCH * NUM_HEADS);
    attn_mma_kernel<<<agrid, 256, ATT_SMEM>>>();

    // 3) output projection
    dim3 ogrid(D_MODEL / 256, MROWS / 128, 1);
    o_gemm_kernel<<<ogrid, 256, GEMM_SMEM>>>(Wo, out);
}

// round 6
// speedup vs baseline: 1.2547x; 1.2547x over previous
#include <cuda_runtime.h>
#include <math.h>
#include <stdint.h>

#define D_MODEL   1024
#define NUM_HEADS 16
#define HEAD_DIM  64
#define BATCH     2
#define SEQ       2048
#define MROWS     (BATCH*SEQ)   /* 4096 */

// ---------------------------------------------------------------------------
// Scratch (allocation-free: __device__ globals)
// ---------------------------------------------------------------------------
__device__ float g_Q[MROWS * D_MODEL];
__device__ float g_K[MROWS * D_MODEL];
__device__ float g_V[MROWS * D_MODEL];
__device__ float g_AO[MROWS * D_MODEL];

extern __shared__ uint32_t dynsmem[];

// ---------------------------------------------------------------------------
// helpers
// ---------------------------------------------------------------------------
__device__ __forceinline__ uint32_t smem_u32(const void* p) {
    uint32_t a;
    asm("{ .reg .u64 t; cvta.to.shared.u64 t, %1; cvt.u32.u64 %0, t; }" : "=r"(a) : "l"(p));
    return a;
}
__device__ __forceinline__ uint32_t f2tf32(float f) {
    uint32_t r;
    asm("cvt.rna.tf32.f32 %0, %1;" : "=r"(r) : "f"(f));
    return r;
}
__device__ __forceinline__ void cpasync16(uint32_t s, const void* g) {
    asm volatile("cp.async.ca.shared.global [%0], [%1], 16;" :: "r"(s), "l"(g) : "memory");
}
__device__ __forceinline__ void cp_commit() { asm volatile("cp.async.commit_group;" ::: "memory"); }
__device__ __forceinline__ void cp_wait1()  { asm volatile("cp.async.wait_group 1;" ::: "memory"); }
__device__ __forceinline__ void cp_wait0()  { asm volatile("cp.async.wait_group 0;" ::: "memory"); }

__device__ __forceinline__ void mma_tf32(float c[4], uint32_t a0, uint32_t a1,
                                         uint32_t a2, uint32_t a3,
                                         uint32_t b0, uint32_t b1) {
    asm volatile(
        "mma.sync.aligned.m16n8k8.row.col.f32.tf32.tf32.f32 "
        "{%0,%1,%2,%3}, {%4,%5,%6,%7}, {%8,%9}, {%0,%1,%2,%3};"
        : "+f"(c[0]), "+f"(c[1]), "+f"(c[2]), "+f"(c[3])
        : "r"(a0), "r"(a1), "r"(a2), "r"(a3), "r"(b0), "r"(b1));
}

// ---------------------------------------------------------------------------
// tf32 mma.sync GEMM core (Round-3 proven config: 128x128, warp 64x32)
// with optional fused RoPE epilogue for Q/K projections.
// ---------------------------------------------------------------------------
#define BK       16
#define ASTRIDE  20
#define NTILES   (D_MODEL / BK)   /* 64 */

__device__ __forceinline__ void gemm_mma_core(const float* __restrict__ A,
                                              const float* __restrict__ W,
                                              float* __restrict__ C,
                                              const int* __restrict__ pos,
                                              int apply_rope)
{
    __shared__ __align__(16) float As[2][128 * ASTRIDE];
    __shared__ __align__(16) float Bs[2][128 * ASTRIDE];

    const int tid   = threadIdx.x;
    const int lane  = tid & 31;
    const int wid   = tid >> 5;
    const int warpM = wid & 1;
    const int warpN = wid >> 1;
    const int gid   = lane >> 2;
    const int tig   = lane & 3;
    const int m0    = blockIdx.y * 128;
    const int n0    = blockIdx.x * 128;

    const uint32_t sA[2] = { smem_u32(As[0]), smem_u32(As[1]) };
    const uint32_t sB[2] = { smem_u32(Bs[0]), smem_u32(Bs[1]) };

    const int r0 = tid >> 2;
    const int r1 = (tid + 256) >> 2;
    const int c4 = (tid & 3) * 4;

    float acc[4][4][4];
#pragma unroll
    for (int i = 0; i < 4; i++)
#pragma unroll
        for (int j = 0; j < 4; j++)
#pragma unroll
            for (int q = 0; q < 4; q++) acc[i][j][q] = 0.0f;

    cpasync16(sA[0] + (uint32_t)(r0 * ASTRIDE + c4) * 4, &A[(size_t)(m0 + r0) * D_MODEL + c4]);
    cpasync16(sB[0] + (uint32_t)(r0 * ASTRIDE + c4) * 4, &W[(size_t)(n0 + r0) * D_MODEL + c4]);
    cpasync16(sA[0] + (uint32_t)(r1 * ASTRIDE + c4) * 4, &A[(size_t)(m0 + r1) * D_MODEL + c4]);
    cpasync16(sB[0] + (uint32_t)(r1 * ASTRIDE + c4) * 4, &W[(size_t)(n0 + r1) * D_MODEL + c4]);
    cp_commit();

    int buf = 0;
    for (int t = 0; t < NTILES; t++) {
        if (t + 1 < NTILES) {
            const int k0 = (t + 1) * BK;
            const int nb = buf ^ 1;
            cpasync16(sA[nb] + (uint32_t)(r0 * ASTRIDE + c4) * 4, &A[(size_t)(m0 + r0) * D_MODEL + k0 + c4]);
            cpasync16(sB[nb] + (uint32_t)(r0 * ASTRIDE + c4) * 4, &W[(size_t)(n0 + r0) * D_MODEL + k0 + c4]);
            cpasync16(sA[nb] + (uint32_t)(r1 * ASTRIDE + c4) * 4, &A[(size_t)(m0 + r1) * D_MODEL + k0 + c4]);
            cpasync16(sB[nb] + (uint32_t)(r1 * ASTRIDE + c4) * 4, &W[(size_t)(n0 + r1) * D_MODEL + k0 + c4]);
            cp_commit();
            cp_wait1();
        } else {
            cp_wait0();
        }
        __syncthreads();

        const float* At = As[buf];
        const float* Bt = Bs[buf];
#pragma unroll
        for (int ks = 0; ks < 2; ks++) {
            const int k0 = ks * 8;
            uint32_t af[4][4], bf[4][2];
#pragma unroll
            for (int mf = 0; mf < 4; mf++) {
                const int ra = warpM * 64 + mf * 16 + gid;
                af[mf][0] = f2tf32(At[ra * ASTRIDE + k0 + tig]);
                af[mf][1] = f2tf32(At[(ra + 8) * ASTRIDE + k0 + tig]);
                af[mf][2] = f2tf32(At[ra * ASTRIDE + k0 + tig + 4]);
                af[mf][3] = f2tf32(At[(ra + 8) * ASTRIDE + k0 + tig + 4]);
            }
#pragma unroll
            for (int nf = 0; nf < 4; nf++) {
                const int rb = warpN * 32 + nf * 8 + gid;
                bf[nf][0] = f2tf32(Bt[rb * ASTRIDE + k0 + tig]);
                bf[nf][1] = f2tf32(Bt[rb * ASTRIDE + k0 + tig + 4]);
            }
#pragma unroll
            for (int mf = 0; mf < 4; mf++)
#pragma unroll
                for (int nf = 0; nf < 4; nf++)
                    mma_tf32(acc[mf][nf], af[mf][0], af[mf][1], af[mf][2], af[mf][3],
                             bf[nf][0], bf[nf][1]);
        }
        __syncthreads();
        buf ^= 1;
    }

    // ---- epilogue (optional fused RoPE) ----
    // column pair (c, c+1) with c even: rotation pair; freq index
    // i = ((col within head)/2) = (warpN&1)*16 + nf*4 + tig
    float ivf[4];
    if (apply_rope) {
#pragma unroll
        for (int nf = 0; nf < 4; nf++) {
            const int i = (warpN & 1) * 16 + nf * 4 + tig;
            ivf[nf] = (float)exp(-(double)i * (9.210340371976184 / 32.0));
        }
    }

#pragma unroll
    for (int mf = 0; mf < 4; mf++) {
        const int r = m0 + warpM * 64 + mf * 16 + gid;
        float p0 = 0.f, p8 = 0.f;
        if (apply_rope) {
            p0 = (float)pos[r & (SEQ - 1)];
            p8 = (float)pos[(r + 8) & (SEQ - 1)];
        }
#pragma unroll
        for (int nf = 0; nf < 4; nf++) {
            const int c = n0 + warpN * 32 + nf * 8 + 2 * tig;
            float x0 = acc[mf][nf][0], x1 = acc[mf][nf][1];
            float x2 = acc[mf][nf][2], x3 = acc[mf][nf][3];
            if (apply_rope) {
                float sn, cs;
                sincosf(p0 * ivf[nf], &sn, &cs);
                float t0 = x0 * cs - x1 * sn;
                float t1 = x0 * sn + x1 * cs;
                x0 = t0; x1 = t1;
                sincosf(p8 * ivf[nf], &sn, &cs);
                t0 = x2 * cs - x3 * sn;
                t1 = x2 * sn + x3 * cs;
                x2 = t0; x3 = t1;
            }
            *(float2*)&C[(size_t)r * D_MODEL + c]       = make_float2(x0, x1);
            *(float2*)&C[(size_t)(r + 8) * D_MODEL + c] = make_float2(x2, x3);
        }
    }
}

__global__ void __launch_bounds__(256)
qkv_gemm_kernel(const float* __restrict__ X,
                const float* __restrict__ Wq,
                const float* __restrict__ Wk,
                const float* __restrict__ Wv,
                const int* __restrict__ pos)
{
    const float* W = (blockIdx.z == 0) ? Wq : (blockIdx.z == 1) ? Wk : Wv;
    float* C       = (blockIdx.z == 0) ? g_Q : (blockIdx.z == 1) ? g_K : g_V;
    gemm_mma_core(X, W, C, pos, blockIdx.z < 2);
}

__global__ void __launch_bounds__(256)
o_gemm_kernel(const float* __restrict__ Wo, float* __restrict__ out)
{
    gemm_mma_core(g_AO, Wo, out, nullptr, 0);
}

// ---------------------------------------------------------------------------
// Causal flash attention, m16n8k8 tf32 mma, cp.async double-buffered K/V
// (unchanged from Round 5).
// ---------------------------------------------------------------------------
#define A_BM     128
#define A_BN     64
#define A_STR    68
#define AK_U32   (A_BN * A_STR)
#define ABUF_U32 (2 * AK_U32)
#define APS_OFF  (2 * ABUF_U32)
#define ATT_SMEM ((2 * ABUF_U32 + A_BM * A_STR) * 4)   /* 104448 B */

__global__ void __launch_bounds__(256)
attn_mma_kernel()
{
    uint32_t* sm = dynsmem;
    const int tid  = threadIdx.x;
    const int lane = tid & 31;
    const int w    = tid >> 5;
    const int gid  = lane >> 2;
    const int tig  = lane & 3;
    const int bh   = blockIdx.y;
    const int b    = bh >> 4;
    const int h    = bh & 15;
    const int m0   = blockIdx.x * A_BM;

    const float* __restrict__ Qb = g_Q + (size_t)b * SEQ * D_MODEL + h * HEAD_DIM;
    const float* __restrict__ Kb = g_K + (size_t)b * SEQ * D_MODEL + h * HEAD_DIM;
    const float* __restrict__ Vb = g_V + (size_t)b * SEQ * D_MODEL + h * HEAD_DIM;

    const uint32_t smbase = smem_u32(sm);
    uint32_t* Ps = sm + APS_OFF;

    auto issue = [&](int ti, int bb) {
        const int kt = ti * A_BN;
        const uint32_t base = smbase + (uint32_t)(bb * ABUF_U32) * 4;
#pragma unroll
        for (int it = 0; it < 4; it++) {
            const int id  = tid + it * 256;
            const int row = id >> 4;
            const int c4  = (id & 15) * 4;
            cpasync16(base + (uint32_t)(row * A_STR + c4) * 4,
                      &Kb[(size_t)(kt + row) * D_MODEL + c4]);
            cpasync16(base + (uint32_t)(AK_U32 + row * A_STR + c4) * 4,
                      &Vb[(size_t)(kt + row) * D_MODEL + c4]);
        }
        cp_commit();
    };

    issue(0, 0);

    const int r0 = m0 + w * 16 + gid;
    const int r1 = r0 + 8;

    uint32_t qf[8][4];
#pragma unroll
    for (int kc = 0; kc < 8; kc++) {
        qf[kc][0] = f2tf32(0.125f * Qb[(size_t)r0 * D_MODEL + kc * 8 + tig]);
        qf[kc][1] = f2tf32(0.125f * Qb[(size_t)r1 * D_MODEL + kc * 8 + tig]);
        qf[kc][2] = f2tf32(0.125f * Qb[(size_t)r0 * D_MODEL + kc * 8 + tig + 4]);
        qf[kc][3] = f2tf32(0.125f * Qb[(size_t)r1 * D_MODEL + kc * 8 + tig + 4]);
    }

    float oacc[8][4];
#pragma unroll
    for (int nf = 0; nf < 8; nf++)
#pragma unroll
        for (int q = 0; q < 4; q++) oacc[nf][q] = 0.0f;
    float m_a = -1e30f, m_b = -1e30f, l_a = 0.0f, l_b = 0.0f;

    const int nt = (m0 + A_BM) / A_BN;

    for (int ti = 0; ti < nt; ti++) {
        const int bb = ti & 1;
        const int kt = ti * A_BN;
        cp_wait0();
        __syncthreads();
        if (ti + 1 < nt) issue(ti + 1, bb ^ 1);

        {
            uint32_t* bp = sm + bb * ABUF_U32;
#pragma unroll
            for (int it = 0; it < 8; it++) {
                const int id   = (it < 4) ? tid + it * 256 : tid + (it - 4) * 256;
                const int mo   = (it < 4) ? 0 : AK_U32;
                const int row  = id >> 4;
                const int c4   = (id & 15) * 4;
                const int off  = mo + row * A_STR + c4;
                float4 v = *(float4*)&bp[off];
                uint4 u;
                u.x = f2tf32(v.x); u.y = f2tf32(v.y);
                u.z = f2tf32(v.z); u.w = f2tf32(v.w);
                *(uint4*)&bp[off] = u;
            }
        }
        __syncthreads();

        const uint32_t* Ks = sm + bb * ABUF_U32;
        const uint32_t* Vs = Ks + AK_U32;

        float sacc[8][4];
#pragma unroll
        for (int nf = 0; nf < 8; nf++)
#pragma unroll
            for (int q = 0; q < 4; q++) sacc[nf][q] = 0.0f;

#pragma unroll
        for (int kc = 0; kc < 8; kc++) {
            uint32_t bf[8][2];
#pragma unroll
            for (int nf = 0; nf < 8; nf++) {
                const int rb = nf * 8 + gid;
                bf[nf][0] = Ks[rb * A_STR + kc * 8 + tig];
                bf[nf][1] = Ks[rb * A_STR + kc * 8 + tig + 4];
            }
#pragma unroll
            for (int nf = 0; nf < 8; nf++)
                mma_tf32(sacc[nf], qf[kc][0], qf[kc][1], qf[kc][2], qf[kc][3],
                         bf[nf][0], bf[nf][1]);
        }

        if (kt + A_BN - 1 > m0) {
#pragma unroll
            for (int nf = 0; nf < 8; nf++) {
                const int c = kt + nf * 8 + 2 * tig;
                if (c > r0)     sacc[nf][0] = -1e30f;
                if (c + 1 > r0) sacc[nf][1] = -1e30f;
                if (c > r1)     sacc[nf][2] = -1e30f;
                if (c + 1 > r1) sacc[nf][3] = -1e30f;
            }
        }

        float mx_a = -1e30f, mx_b = -1e30f;
#pragma unroll
        for (int nf = 0; nf < 8; nf++) {
            mx_a = fmaxf(mx_a, fmaxf(sacc[nf][0], sacc[nf][1]));
            mx_b = fmaxf(mx_b, fmaxf(sacc[nf][2], sacc[nf][3]));
        }
        mx_a = fmaxf(mx_a, __shfl_xor_sync(0xFFFFFFFFu, mx_a, 1));
        mx_a = fmaxf(mx_a, __shfl_xor_sync(0xFFFFFFFFu, mx_a, 2));
        mx_b = fmaxf(mx_b, __shfl_xor_sync(0xFFFFFFFFu, mx_b, 1));
        mx_b = fmaxf(mx_b, __shfl_xor_sync(0xFFFFFFFFu, mx_b, 2));

        const float mna = fmaxf(m_a, mx_a);
        const float mnb = fmaxf(m_b, mx_b);
        const float ca  = __expf(m_a - mna);
        const float cb  = __expf(m_b - mnb);
        m_a = mna; m_b = mnb;

        float sa = 0.0f, sb = 0.0f;
#pragma unroll
        for (int nf = 0; nf < 8; nf++) {
            sacc[nf][0] = __expf(sacc[nf][0] - mna);
            sacc[nf][1] = __expf(sacc[nf][1] - mna);
            sacc[nf][2] = __expf(sacc[nf][2] - mnb);
            sacc[nf][3] = __expf(sacc[nf][3] - mnb);
            sa += sacc[nf][0] + sacc[nf][1];
            sb += sacc[nf][2] + sacc[nf][3];
        }
        sa += __shfl_xor_sync(0xFFFFFFFFu, sa, 1);
        sa += __shfl_xor_sync(0xFFFFFFFFu, sa, 2);
        sb += __shfl_xor_sync(0xFFFFFFFFu, sb, 1);
        sb += __shfl_xor_sync(0xFFFFFFFFu, sb, 2);
        l_a = l_a * ca + sa;
        l_b = l_b * cb + sb;
#pragma unroll
        for (int nf = 0; nf < 8; nf++) {
            oacc[nf][0] *= ca; oacc[nf][1] *= ca;
            oacc[nf][2] *= cb; oacc[nf][3] *= cb;
        }

        const int pr0 = w * 16 + gid;
#pragma unroll
        for (int nf = 0; nf < 8; nf++) {
            const int c = nf * 8 + 2 * tig;
            asm volatile("st.shared.v2.b32 [%0], {%1,%2};"
                :: "r"(smem_u32(&Ps[pr0 * A_STR + c])),
                   "r"(f2tf32(sacc[nf][0])), "r"(f2tf32(sacc[nf][1])) : "memory");
            asm volatile("st.shared.v2.b32 [%0], {%1,%2};"
                :: "r"(smem_u32(&Ps[(pr0 + 8) * A_STR + c])),
                   "r"(f2tf32(sacc[nf][2])), "r"(f2tf32(sacc[nf][3])) : "memory");
        }
        __syncwarp();

#pragma unroll
        for (int kc = 0; kc < 8; kc++) {
            const uint32_t a0 = Ps[pr0 * A_STR + kc * 8 + tig];
            const uint32_t a1 = Ps[(pr0 + 8) * A_STR + kc * 8 + tig];
            const uint32_t a2 = Ps[pr0 * A_STR + kc * 8 + tig + 4];
            const uint32_t a3 = Ps[(pr0 + 8) * A_STR + kc * 8 + tig + 4];
            uint32_t bf[8][2];
#pragma unroll
            for (int nf = 0; nf < 8; nf++) {
                bf[nf][0] = Vs[(kc * 8 + tig) * A_STR + nf * 8 + gid];
                bf[nf][1] = Vs[(kc * 8 + tig + 4) * A_STR + nf * 8 + gid];
            }
#pragma unroll
            for (int nf = 0; nf < 8; nf++)
                mma_tf32(oacc[nf], a0, a1, a2, a3, bf[nf][0], bf[nf][1]);
        }
    }

    const float ila = 1.0f / l_a;
    const float ilb = 1.0f / l_b;
    float* oa = g_AO + (size_t)(b * SEQ + r0) * D_MODEL + h * HEAD_DIM;
    float* ob = g_AO + (size_t)(b * SEQ + r1) * D_MODEL + h * HEAD_DIM;
#pragma unroll
    for (int nf = 0; nf < 8; nf++) {
        const int c = nf * 8 + 2 * tig;
        *(float2*)&oa[c] = make_float2(oacc[nf][0] * ila, oacc[nf][1] * ila);
        *(float2*)&ob[c] = make_float2(oacc[nf][2] * ilb, oacc[nf][3] * ilb);
    }
}

// ---------------------------------------------------------------------------
// Launch
// ---------------------------------------------------------------------------
extern "C" void kernel_launch(void* const* d_in, const int* in_sizes, int n_in,
                              void* d_out, int out_size)
{
    const float* X   = (const float*)d_in[0];
    const float* Wq  = (const float*)d_in[1];
    const float* Wk  = (const float*)d_in[2];
    const float* Wv  = (const float*)d_in[3];
    const float* Wo  = (const float*)d_in[4];
    const int*   pos = (const int*)d_in[5];
    float* out = (float*)d_out;

    static int attr_set = 0;
    if (!attr_set) {
        cudaFuncSetAttribute(attn_mma_kernel,
                             cudaFuncAttributeMaxDynamicSharedMemorySize, ATT_SMEM);
        attr_set = 1;
    }

    // 1) QKV projections with fused RoPE on Q/K
    dim3 ggrid(D_MODEL / 128, MROWS / 128, 3);
    qkv_gemm_kernel<<<ggrid, 256>>>(X, Wq, Wk, Wv, pos);

    // 2) causal attention (tf32 mma, async pipeline)
    dim3 agrid(SEQ / A_BM, BATCH * NUM_HEADS);
    attn_mma_kernel<<<agrid, 256, ATT_SMEM>>>();

    // 3) output projection
    dim3 ogrid(D_MODEL / 128, MROWS / 128, 1);
    o_gemm_kernel<<<ogrid, 256>>>(Wo, out);
}